// round 6
// baseline (speedup 1.0000x reference)
#include <cuda_runtime.h>

// ---------------- problem constants ----------------
#define BB 16          // batch
#define TT 20          // timesteps
#define HH 96
#define WW 96
#define CC 3           // in channels
#define FF 4           // filters
#define HP 95          // valid conv out
#define WP 95
#define PH 47          // pooled
#define PW 47
#define NPOS (HP*WP)   // 9025
#define NTHREADS 256
#define SPT 2          // position sub-tiles per CTA (512 positions/CTA)
#define NBLKX 18       // ceil(9025 / 512)
#define NCTAS (NBLKX * BB)   // 288  (<= 2 per SM on 148 SMs -> always co-resident)

// ---------------- persistent device scratch (no allocs allowed) ----------------
__device__ float g_h[2][BB * NPOS * FF];   // ping-pong hidden state
__device__ float g_c[BB * NPOS * FF];      // cell state (updated in place)
__device__ float g_scratch[BB * NBLKX];    // per-block dense partial (written once)
__device__ unsigned g_bar_count = 0;       // global barrier arrival counter
__device__ unsigned g_bar_phase = 0;       // global barrier phase (monotonic)

__device__ __forceinline__ float ftanh(float x) {
    float y;
    asm("tanh.approx.f32 %0, %1;" : "=f"(y) : "f"(x));
    return y;
}
__device__ __forceinline__ float fsig(float x) {
    return fmaf(ftanh(0.5f * x), 0.5f, 0.5f);
}

// Device-wide barrier. Safe because all NCTAS CTAs are co-resident (2/SM max,
// enforced by __launch_bounds__; 288 <= 296 slots). Phase is monotonic across
// graph replays; the caller passes an absolute target = entry_phase + k.
__device__ __forceinline__ void grid_sync(unsigned target) {
    __syncthreads();
    if (threadIdx.x == 0) {
        __threadfence();                                   // release prior writes
        unsigned old = atomicAdd(&g_bar_count, 1u);
        if (old == (unsigned)(NCTAS - 1)) {
            atomicExch(&g_bar_count, 0u);                  // reset for next barrier
            __threadfence();
            atomicAdd(&g_bar_phase, 1u);                   // release all spinners
        } else {
            while (*(volatile unsigned*)&g_bar_phase != target) { }
        }
        __threadfence();                                   // acquire peer writes
    }
    __syncthreads();
}

// Prefetch the 2x2x3 input patch for position p at timestep t into registers.
__device__ __forceinline__ void load_x(int p, int b, int t,
                                       const float* __restrict__ x, float* xv) {
    const int i = p / WP, j = p % WP;
    const float* xb = x + ((((size_t)b * TT + t) * HH + i) * WW + j) * CC;
    #pragma unroll
    for (int q = 0; q < 4; q++) {
        const int di = q >> 1, dj = q & 1;
        const float* xp = xb + (di * WW + dj) * CC;
        #pragma unroll
        for (int ci = 0; ci < CC; ci++) xv[q * 3 + ci] = xp[ci];
    }
}

// One position of one timestep (x patch already in registers). Returns this
// position's dense contribution (maxpool+dot of the h_{t-1} patch, which is
// loaded anyway for the recurrent conv).
__device__ __forceinline__ float step_pos(
    int p, int b, int t, const float* __restrict__ xv,
    const float4* __restrict__ sK, const float4* __restrict__ sRK,
    const float4* __restrict__ sB, const float* __restrict__ dw)
{
    const int i = p / WP;
    const int j = p % WP;

    const float* hprev = g_h[(t + 1) & 1] + (size_t)b * NPOS * FF;
    float*       hnew  = g_h[t & 1]       + (size_t)b * NPOS * FF;
    float*       cc    = g_c              + (size_t)b * NPOS * FF;

    float4 z[4];
    #pragma unroll
    for (int g4 = 0; g4 < 4; g4++) z[g4] = sB[g4];

    // ---- input conv (VALID), x patch in registers ----
    #pragma unroll
    for (int e = 0; e < 12; e++) {
        const float v = xv[e];
        const float4* kw = &sK[e * 4];
        #pragma unroll
        for (int g4 = 0; g4 < 4; g4++) {
            const float4 w = kw[g4];
            z[g4].x += v * w.x; z[g4].y += v * w.y;
            z[g4].z += v * w.z; z[g4].w += v * w.w;
        }
    }

    // ---- recurrent conv (SAME, pad_hi=1): h_prev[i+di, j+dj], zeros OOB ----
    float hv[4][4];
    if (t > 0) {
        #pragma unroll
        for (int q = 0; q < 4; q++) {
            const int di = q >> 1, dj = q & 1;
            const int ii = i + di, jj = j + dj;
            float4 h4 = make_float4(0.f, 0.f, 0.f, 0.f);
            if (ii < HP && jj < WP)
                h4 = *(const float4*)(hprev + ((size_t)(ii * WP + jj)) * 4);
            hv[q][0] = h4.x; hv[q][1] = h4.y; hv[q][2] = h4.z; hv[q][3] = h4.w;
            #pragma unroll
            for (int f = 0; f < 4; f++) {
                const float v = hv[q][f];
                const float4* rw = &sRK[(q * 4 + f) * 4];
                #pragma unroll
                for (int g4 = 0; g4 < 4; g4++) {
                    const float4 w = rw[g4];
                    z[g4].x += v * w.x; z[g4].y += v * w.y;
                    z[g4].z += v * w.z; z[g4].w += v * w.w;
                }
            }
        }
    }

    // ---- gates (order i,f,g,o) + state update ----
    float4 cold = make_float4(0.f, 0.f, 0.f, 0.f);
    if (t > 0) cold = *(const float4*)(cc + (size_t)p * 4);
    const float zi[4] = {z[0].x, z[0].y, z[0].z, z[0].w};
    const float zf[4] = {z[1].x, z[1].y, z[1].z, z[1].w};
    const float zg[4] = {z[2].x, z[2].y, z[2].z, z[2].w};
    const float zo[4] = {z[3].x, z[3].y, z[3].z, z[3].w};
    const float cprev[4] = {cold.x, cold.y, cold.z, cold.w};
    float cn[4], hn[4];
    #pragma unroll
    for (int f = 0; f < 4; f++) {
        const float ig = fsig(zi[f]);
        const float fg = fsig(zf[f]);
        const float gg = ftanh(zg[f]);
        const float og = fsig(zo[f]);
        const float c2 = fg * cprev[f] + ig * gg;
        cn[f] = c2;
        hn[f] = og * ftanh(c2);
    }
    *(float4*)(cc   + (size_t)p * 4) = make_float4(cn[0], cn[1], cn[2], cn[3]);
    *(float4*)(hnew + (size_t)p * 4) = make_float4(hn[0], hn[1], hn[2], hn[3]);

    // ---- maxpool(2x2) + dense contribution of h_{t-1} (patch already loaded) ----
    float contrib = 0.f;
    if (t > 0 && ((i & 1) == 0) && ((j & 1) == 0) && i < 94 && j < 94) {
        const int ph = i >> 1, pw = j >> 1;
        const float4 w4 = *(const float4*)(dw + ((((size_t)(t - 1) * PH + ph) * PW + pw) * 4));
        const float m0 = fmaxf(fmaxf(hv[0][0], hv[1][0]), fmaxf(hv[2][0], hv[3][0]));
        const float m1 = fmaxf(fmaxf(hv[0][1], hv[1][1]), fmaxf(hv[2][1], hv[3][1]));
        const float m2 = fmaxf(fmaxf(hv[0][2], hv[1][2]), fmaxf(hv[2][2], hv[3][2]));
        const float m3 = fmaxf(fmaxf(hv[0][3], hv[1][3]), fmaxf(hv[2][3], hv[3][3]));
        contrib = m0 * w4.x + m1 * w4.y + m2 * w4.z + m3 * w4.w;
    }
    return contrib;
}

// Dense contribution of the final hidden state h_{T-1} at position p.
__device__ __forceinline__ float pool_last(int p, int b, const float* __restrict__ dw)
{
    const int i = p / WP;
    const int j = p % WP;
    if ((i & 1) | (j & 1) || i >= 94 || j >= 94) return 0.f;
    const float* hlast = g_h[(TT - 1) & 1] + (size_t)b * NPOS * FF;
    float m0 = -1e30f, m1 = -1e30f, m2 = -1e30f, m3 = -1e30f;
    #pragma unroll
    for (int di = 0; di < 2; di++)
    #pragma unroll
    for (int dj = 0; dj < 2; dj++) {
        const float4 h4 = *(const float4*)(hlast + ((size_t)((i + di) * WP + (j + dj))) * 4);
        m0 = fmaxf(m0, h4.x); m1 = fmaxf(m1, h4.y);
        m2 = fmaxf(m2, h4.z); m3 = fmaxf(m3, h4.w);
    }
    const int ph = i >> 1, pw = j >> 1;
    const float4 w4 = *(const float4*)(dw + ((((size_t)(TT - 1) * PH + ph) * PW + pw) * 4));
    return m0 * w4.x + m1 * w4.y + m2 * w4.z + m3 * w4.w;
}

__global__ void __launch_bounds__(NTHREADS, 2)
persistent_kernel(const float* __restrict__ x,
                  const float4* __restrict__ Kw,    // 48 float4
                  const float4* __restrict__ RKw,   // 64 float4
                  const float4* __restrict__ bias,  // 4 float4
                  const float* __restrict__ dw,
                  const float* __restrict__ db,
                  float* __restrict__ out)
{
    __shared__ float4 sK[48];
    __shared__ float4 sRK[64];
    __shared__ float4 sB[4];
    __shared__ float warpsum[NTHREADS / 32];

    const int tid = threadIdx.x;
    const int b   = blockIdx.y;
    const int blk = blockIdx.x;

    // Barrier phase snapshot: every CTA reads this before arriving at barrier 1,
    // and the phase cannot advance until all have arrived -> all see the same value.
    const unsigned base = *(volatile unsigned*)&g_bar_phase;

    if (tid < 48) sK[tid]  = Kw[tid];
    if (tid < 64) sRK[tid] = RKw[tid];
    if (tid < 4)  sB[tid]  = bias[tid];
    __syncthreads();

    const int p0 = blk * (NTHREADS * SPT) + tid;
    const int p1 = p0 + NTHREADS;
    const bool a0 = (p0 < NPOS);
    const bool a1 = (p1 < NPOS);

    float xv0[12], xv1[12];
    if (a0) load_x(p0, b, 0, x, xv0);
    if (a1) load_x(p1, b, 0, x, xv1);

    float dense_acc = 0.f;   // this thread's dense partial across ALL timesteps

    for (int t = 0; t < TT; t++) {
        if (a0) dense_acc += step_pos(p0, b, t, xv0, sK, sRK, sB, dw);
        if (a1) dense_acc += step_pos(p1, b, t, xv1, sK, sRK, sB, dw);
        // Prefetch next timestep's x BEFORE the barrier: its latency hides
        // behind the barrier wait instead of the post-barrier critical path.
        if (t + 1 < TT) {
            if (a0) load_x(p0, b, t + 1, x, xv0);
            if (a1) load_x(p1, b, t + 1, x, xv1);
        }
        grid_sync(base + (unsigned)(t + 1));   // h_t fully written before step t+1
    }

    // Epilogue: pool+dense of h_{T-1} (its stores were fenced by the last sync).
    if (a0) dense_acc += pool_last(p0, b, dw);
    if (a1) dense_acc += pool_last(p1, b, dw);

    // Deterministic block reduction -> one scratch write per CTA.
    #pragma unroll
    for (int off = 16; off > 0; off >>= 1)
        dense_acc += __shfl_down_sync(0xFFFFFFFFu, dense_acc, off);
    if ((tid & 31) == 0) warpsum[tid >> 5] = dense_acc;
    __syncthreads();
    if (tid == 0) {
        float s = 0.f;
        #pragma unroll
        for (int w = 0; w < NTHREADS / 32; w++) s += warpsum[w];
        g_scratch[b * NBLKX + blk] = s;
    }

    grid_sync(base + (unsigned)(TT + 1));

    // One CTA per batch emits the output (fixed summation order).
    if (blk == 0 && tid == 0) {
        float acc = 0.f;
        for (int k = 0; k < NBLKX; k++) acc += g_scratch[b * NBLKX + k];
        out[b] = acc + db[0];
    }
}

extern "C" void kernel_launch(void* const* d_in, const int* in_sizes, int n_in,
                              void* d_out, int out_size) {
    const float*  x    = (const float*)d_in[0];
    const float4* Kw   = (const float4*)d_in[1];
    const float4* RKw  = (const float4*)d_in[2];
    const float4* bias = (const float4*)d_in[3];
    const float*  dw   = (const float*)d_in[4];
    const float*  db   = (const float*)d_in[5];
    float* out = (float*)d_out;

    dim3 grid(NBLKX, BB);
    persistent_kernel<<<grid, NTHREADS>>>(x, Kw, RKw, bias, dw, db, out);
}

// round 7
// speedup vs baseline: 3.1228x; 3.1228x over previous
#include <cuda_runtime.h>

// ---------------- problem constants ----------------
#define BB 16          // batch
#define TT 20          // timesteps
#define HH 96
#define WW 96
#define CC 3           // in channels
#define FF 4           // filters
#define HP 95          // valid conv out
#define WP 95
#define PH 47          // pooled
#define PW 47
#define NPOS (HP*WP)   // 9025
#define NTHREADS 256
#define NBLKX 36       // ceil(9025 / 256)
#define NCTAS (NBLKX * BB)   // 576; 148 SMs * 4 CTAs/SM = 592 slots -> all co-resident

// ---------------- persistent device scratch (no allocs allowed) ----------------
__device__ float g_h[2][BB * NPOS * FF];   // ping-pong hidden state
__device__ float g_c[BB * NPOS * FF];      // cell state (updated in place)
__device__ float g_scratch[BB * NBLKX];    // per-block dense partial (written once)
__device__ unsigned g_bar_count = 0;       // global barrier arrival counter
__device__ unsigned g_bar_phase = 0;       // global barrier phase (monotonic)

__device__ __forceinline__ float ftanh(float x) {
    float y;
    asm("tanh.approx.f32 %0, %1;" : "=f"(y) : "f"(x));
    return y;
}
__device__ __forceinline__ float fsig(float x) {
    return fmaf(ftanh(0.5f * x), 0.5f, 0.5f);
}

// Device-wide barrier. Safe: all NCTAS CTAs are co-resident by construction
// (__launch_bounds__(256,4) -> 4 CTAs/SM; 576 <= 592). Phase is monotonic
// across graph replays; caller passes absolute target = entry_phase + k.
__device__ __forceinline__ void grid_sync(unsigned target) {
    __syncthreads();
    if (threadIdx.x == 0) {
        __threadfence();                                   // release prior writes
        unsigned old = atomicAdd(&g_bar_count, 1u);
        if (old == (unsigned)(NCTAS - 1)) {
            atomicExch(&g_bar_count, 0u);                  // reset for next barrier
            __threadfence();
            atomicAdd(&g_bar_phase, 1u);                   // release all spinners
        } else {
            while (*(volatile unsigned*)&g_bar_phase != target)
                __nanosleep(20);
        }
        __threadfence();                                   // acquire peer writes
    }
    __syncthreads();
}

// One position of one timestep (x loaded here; identical to the proven R4 body).
// Returns this position's dense contribution (maxpool+dot of the h_{t-1} patch,
// which is loaded anyway for the recurrent conv).
__device__ __forceinline__ float step_pos(
    int p, int b, int t,
    const float* __restrict__ x,
    const float4* __restrict__ sK, const float4* __restrict__ sRK,
    const float4* __restrict__ sB, const float* __restrict__ dw)
{
    const int i = p / WP;
    const int j = p % WP;

    const float* hprev = g_h[(t + 1) & 1] + (size_t)b * NPOS * FF;
    float*       hnew  = g_h[t & 1]       + (size_t)b * NPOS * FF;
    float*       cc    = g_c              + (size_t)b * NPOS * FF;

    float4 z[4];
    #pragma unroll
    for (int g4 = 0; g4 < 4; g4++) z[g4] = sB[g4];

    // ---- input conv (VALID): rows i,i+1 / cols j,j+1 always in-bounds ----
    const float* xb = x + ((((size_t)b * TT + t) * HH + i) * WW + j) * CC;
    #pragma unroll
    for (int q = 0; q < 4; q++) {
        const int di = q >> 1, dj = q & 1;
        const float* xp = xb + (di * WW + dj) * CC;
        #pragma unroll
        for (int ci = 0; ci < CC; ci++) {
            const float v = xp[ci];
            const float4* kw = &sK[(q * 3 + ci) * 4];
            #pragma unroll
            for (int g4 = 0; g4 < 4; g4++) {
                const float4 w = kw[g4];
                z[g4].x += v * w.x; z[g4].y += v * w.y;
                z[g4].z += v * w.z; z[g4].w += v * w.w;
            }
        }
    }

    // ---- recurrent conv (SAME, pad_hi=1): h_prev[i+di, j+dj], zeros OOB ----
    float hv[4][4];
    if (t > 0) {
        #pragma unroll
        for (int q = 0; q < 4; q++) {
            const int di = q >> 1, dj = q & 1;
            const int ii = i + di, jj = j + dj;
            float4 h4 = make_float4(0.f, 0.f, 0.f, 0.f);
            if (ii < HP && jj < WP)
                h4 = *(const float4*)(hprev + ((size_t)(ii * WP + jj)) * 4);
            hv[q][0] = h4.x; hv[q][1] = h4.y; hv[q][2] = h4.z; hv[q][3] = h4.w;
            #pragma unroll
            for (int f = 0; f < 4; f++) {
                const float v = hv[q][f];
                const float4* rw = &sRK[(q * 4 + f) * 4];
                #pragma unroll
                for (int g4 = 0; g4 < 4; g4++) {
                    const float4 w = rw[g4];
                    z[g4].x += v * w.x; z[g4].y += v * w.y;
                    z[g4].z += v * w.z; z[g4].w += v * w.w;
                }
            }
        }
    }

    // ---- gates (order i,f,g,o) + state update ----
    float4 cold = make_float4(0.f, 0.f, 0.f, 0.f);
    if (t > 0) cold = *(const float4*)(cc + (size_t)p * 4);
    const float zi[4] = {z[0].x, z[0].y, z[0].z, z[0].w};
    const float zf[4] = {z[1].x, z[1].y, z[1].z, z[1].w};
    const float zg[4] = {z[2].x, z[2].y, z[2].z, z[2].w};
    const float zo[4] = {z[3].x, z[3].y, z[3].z, z[3].w};
    const float cprev[4] = {cold.x, cold.y, cold.z, cold.w};
    float cn[4], hn[4];
    #pragma unroll
    for (int f = 0; f < 4; f++) {
        const float ig = fsig(zi[f]);
        const float fg = fsig(zf[f]);
        const float gg = ftanh(zg[f]);
        const float og = fsig(zo[f]);
        const float c2 = fg * cprev[f] + ig * gg;
        cn[f] = c2;
        hn[f] = og * ftanh(c2);
    }
    *(float4*)(cc   + (size_t)p * 4) = make_float4(cn[0], cn[1], cn[2], cn[3]);
    *(float4*)(hnew + (size_t)p * 4) = make_float4(hn[0], hn[1], hn[2], hn[3]);

    // ---- maxpool(2x2) + dense contribution of h_{t-1} (patch already loaded) ----
    float contrib = 0.f;
    if (t > 0 && ((i & 1) == 0) && ((j & 1) == 0) && i < 94 && j < 94) {
        const int ph = i >> 1, pw = j >> 1;
        const float4 w4 = *(const float4*)(dw + ((((size_t)(t - 1) * PH + ph) * PW + pw) * 4));
        const float m0 = fmaxf(fmaxf(hv[0][0], hv[1][0]), fmaxf(hv[2][0], hv[3][0]));
        const float m1 = fmaxf(fmaxf(hv[0][1], hv[1][1]), fmaxf(hv[2][1], hv[3][1]));
        const float m2 = fmaxf(fmaxf(hv[0][2], hv[1][2]), fmaxf(hv[2][2], hv[3][2]));
        const float m3 = fmaxf(fmaxf(hv[0][3], hv[1][3]), fmaxf(hv[2][3], hv[3][3]));
        contrib = m0 * w4.x + m1 * w4.y + m2 * w4.z + m3 * w4.w;
    }
    return contrib;
}

// Dense contribution of the final hidden state h_{T-1} at position p.
__device__ __forceinline__ float pool_last(int p, int b, const float* __restrict__ dw)
{
    const int i = p / WP;
    const int j = p % WP;
    if ((i & 1) | (j & 1) || i >= 94 || j >= 94) return 0.f;
    const float* hlast = g_h[(TT - 1) & 1] + (size_t)b * NPOS * FF;
    float m0 = -1e30f, m1 = -1e30f, m2 = -1e30f, m3 = -1e30f;
    #pragma unroll
    for (int di = 0; di < 2; di++)
    #pragma unroll
    for (int dj = 0; dj < 2; dj++) {
        const float4 h4 = *(const float4*)(hlast + ((size_t)((i + di) * WP + (j + dj))) * 4);
        m0 = fmaxf(m0, h4.x); m1 = fmaxf(m1, h4.y);
        m2 = fmaxf(m2, h4.z); m3 = fmaxf(m3, h4.w);
    }
    const int ph = i >> 1, pw = j >> 1;
    const float4 w4 = *(const float4*)(dw + ((((size_t)(TT - 1) * PH + ph) * PW + pw) * 4));
    return m0 * w4.x + m1 * w4.y + m2 * w4.z + m3 * w4.w;
}

__global__ void __launch_bounds__(NTHREADS, 4)
persistent_kernel(const float* __restrict__ x,
                  const float4* __restrict__ Kw,    // 48 float4
                  const float4* __restrict__ RKw,   // 64 float4
                  const float4* __restrict__ bias,  // 4 float4
                  const float* __restrict__ dw,
                  const float* __restrict__ db,
                  float* __restrict__ out)
{
    __shared__ float4 sK[48];
    __shared__ float4 sRK[64];
    __shared__ float4 sB[4];
    __shared__ float warpsum[NTHREADS / 32];

    const int tid = threadIdx.x;
    const int b   = blockIdx.y;
    const int blk = blockIdx.x;

    // Phase snapshot: read before this CTA's first arrival; the phase cannot
    // advance until ALL CTAs have arrived (each having read it) -> all equal.
    const unsigned base = *(volatile unsigned*)&g_bar_phase;

    if (tid < 48) sK[tid]  = Kw[tid];
    if (tid < 64) sRK[tid] = RKw[tid];
    if (tid < 4)  sB[tid]  = bias[tid];
    __syncthreads();

    const int p = blk * NTHREADS + tid;
    const bool active = (p < NPOS);

    float dense_acc = 0.f;   // this thread's dense partial across ALL timesteps

    for (int t = 0; t < TT; t++) {
        if (active)
            dense_acc += step_pos(p, b, t, x, sK, sRK, sB, dw);
        grid_sync(base + (unsigned)(t + 1));   // h_t fully written before step t+1
    }

    // Epilogue: pool+dense of h_{T-1} (its stores were fenced by the last sync).
    if (active)
        dense_acc += pool_last(p, b, dw);

    // Deterministic block reduction -> one scratch write per CTA.
    #pragma unroll
    for (int off = 16; off > 0; off >>= 1)
        dense_acc += __shfl_down_sync(0xFFFFFFFFu, dense_acc, off);
    if ((tid & 31) == 0) warpsum[tid >> 5] = dense_acc;
    __syncthreads();
    if (tid == 0) {
        float s = 0.f;
        #pragma unroll
        for (int w = 0; w < NTHREADS / 32; w++) s += warpsum[w];
        g_scratch[b * NBLKX + blk] = s;
    }

    grid_sync(base + (unsigned)(TT + 1));

    // One CTA per batch emits the output (fixed summation order).
    if (blk == 0 && tid == 0) {
        float acc = 0.f;
        for (int k = 0; k < NBLKX; k++) acc += g_scratch[b * NBLKX + k];
        out[b] = acc + db[0];
    }
}

extern "C" void kernel_launch(void* const* d_in, const int* in_sizes, int n_in,
                              void* d_out, int out_size) {
    const float*  x    = (const float*)d_in[0];
    const float4* Kw   = (const float4*)d_in[1];
    const float4* RKw  = (const float4*)d_in[2];
    const float4* bias = (const float4*)d_in[3];
    const float*  dw   = (const float*)d_in[4];
    const float*  db   = (const float*)d_in[5];
    float* out = (float*)d_out;

    dim3 grid(NBLKX, BB);
    persistent_kernel<<<grid, NTHREADS>>>(x, Kw, RKw, bias, dw, db, out);
}

// round 10
// speedup vs baseline: 3.6055x; 1.1546x over previous
#include <cuda_runtime.h>

// ---------------- problem constants ----------------
#define BB 16          // batch
#define TT 20          // timesteps
#define HH 96
#define WW 96
#define CC 3           // in channels
#define FF 4           // filters
#define HP 95          // valid conv out
#define WP 95
#define PH 47          // pooled
#define PW 47
#define NPOS (HP*WP)   // 9025
#define NTHREADS 256
#define NBLKX 36       // ceil(9025 / 256)
#define NCTAS (NBLKX * BB)   // 576; 148 SMs * 4 CTAs/SM = 592 slots -> all co-resident

// ---------------- persistent device scratch (no allocs allowed) ----------------
__device__ float g_h[2][BB * NPOS * FF];     // ping-pong hidden state
__device__ float g_c[BB * NPOS * FF];        // cell state (updated in place)
__device__ float g_scratch[BB * NBLKX];      // per-block dense partial (written once)
// Per-CTA monotonic step flags, padded to 32B sectors to decouple spin traffic.
__device__ volatile unsigned g_flag[BB][NBLKX][8];
__device__ unsigned g_done[BB];              // per-batch arrival counters (self-reset)

__device__ __forceinline__ float ftanh(float x) {
    float y;
    asm("tanh.approx.f32 %0, %1;" : "=f"(y) : "f"(x));
    return y;
}
__device__ __forceinline__ float fsig(float x) {
    return fmaf(ftanh(0.5f * x), 0.5f, 0.5f);
}

// One position of one timestep (proven 64-reg body, unchanged).
// Returns this position's dense contribution (maxpool+dot of the h_{t-1} patch,
// which is loaded anyway for the recurrent conv).
__device__ __forceinline__ float step_pos(
    int p, int b, int t,
    const float* __restrict__ x,
    const float4* __restrict__ sK, const float4* __restrict__ sRK,
    const float4* __restrict__ sB, const float* __restrict__ dw)
{
    const int i = p / WP;
    const int j = p % WP;

    const float* hprev = g_h[(t + 1) & 1] + (size_t)b * NPOS * FF;
    float*       hnew  = g_h[t & 1]       + (size_t)b * NPOS * FF;
    float*       cc    = g_c              + (size_t)b * NPOS * FF;

    float4 z[4];
    #pragma unroll
    for (int g4 = 0; g4 < 4; g4++) z[g4] = sB[g4];

    // ---- input conv (VALID): rows i,i+1 / cols j,j+1 always in-bounds ----
    const float* xb = x + ((((size_t)b * TT + t) * HH + i) * WW + j) * CC;
    #pragma unroll
    for (int q = 0; q < 4; q++) {
        const int di = q >> 1, dj = q & 1;
        const float* xp = xb + (di * WW + dj) * CC;
        #pragma unroll
        for (int ci = 0; ci < CC; ci++) {
            const float v = xp[ci];
            const float4* kw = &sK[(q * 3 + ci) * 4];
            #pragma unroll
            for (int g4 = 0; g4 < 4; g4++) {
                const float4 w = kw[g4];
                z[g4].x += v * w.x; z[g4].y += v * w.y;
                z[g4].z += v * w.z; z[g4].w += v * w.w;
            }
        }
    }

    // ---- recurrent conv (SAME, pad_hi=1): h_prev[i+di, j+dj], zeros OOB ----
    float hv[4][4];
    if (t > 0) {
        #pragma unroll
        for (int q = 0; q < 4; q++) {
            const int di = q >> 1, dj = q & 1;
            const int ii = i + di, jj = j + dj;
            float4 h4 = make_float4(0.f, 0.f, 0.f, 0.f);
            if (ii < HP && jj < WP)
                h4 = *(const float4*)(hprev + ((size_t)(ii * WP + jj)) * 4);
            hv[q][0] = h4.x; hv[q][1] = h4.y; hv[q][2] = h4.z; hv[q][3] = h4.w;
            #pragma unroll
            for (int f = 0; f < 4; f++) {
                const float v = hv[q][f];
                const float4* rw = &sRK[(q * 4 + f) * 4];
                #pragma unroll
                for (int g4 = 0; g4 < 4; g4++) {
                    const float4 w = rw[g4];
                    z[g4].x += v * w.x; z[g4].y += v * w.y;
                    z[g4].z += v * w.z; z[g4].w += v * w.w;
                }
            }
        }
    }

    // ---- gates (order i,f,g,o) + state update ----
    float4 cold = make_float4(0.f, 0.f, 0.f, 0.f);
    if (t > 0) cold = *(const float4*)(cc + (size_t)p * 4);
    const float zi[4] = {z[0].x, z[0].y, z[0].z, z[0].w};
    const float zf[4] = {z[1].x, z[1].y, z[1].z, z[1].w};
    const float zg[4] = {z[2].x, z[2].y, z[2].z, z[2].w};
    const float zo[4] = {z[3].x, z[3].y, z[3].z, z[3].w};
    const float cprev[4] = {cold.x, cold.y, cold.z, cold.w};
    float cn[4], hn[4];
    #pragma unroll
    for (int f = 0; f < 4; f++) {
        const float ig = fsig(zi[f]);
        const float fg = fsig(zf[f]);
        const float gg = ftanh(zg[f]);
        const float og = fsig(zo[f]);
        const float c2 = fg * cprev[f] + ig * gg;
        cn[f] = c2;
        hn[f] = og * ftanh(c2);
    }
    *(float4*)(cc   + (size_t)p * 4) = make_float4(cn[0], cn[1], cn[2], cn[3]);
    *(float4*)(hnew + (size_t)p * 4) = make_float4(hn[0], hn[1], hn[2], hn[3]);

    // ---- maxpool(2x2) + dense contribution of h_{t-1} (patch already loaded) ----
    float contrib = 0.f;
    if (t > 0 && ((i & 1) == 0) && ((j & 1) == 0) && i < 94 && j < 94) {
        const int ph = i >> 1, pw = j >> 1;
        const float4 w4 = *(const float4*)(dw + ((((size_t)(t - 1) * PH + ph) * PW + pw) * 4));
        const float m0 = fmaxf(fmaxf(hv[0][0], hv[1][0]), fmaxf(hv[2][0], hv[3][0]));
        const float m1 = fmaxf(fmaxf(hv[0][1], hv[1][1]), fmaxf(hv[2][1], hv[3][1]));
        const float m2 = fmaxf(fmaxf(hv[0][2], hv[1][2]), fmaxf(hv[2][2], hv[3][2]));
        const float m3 = fmaxf(fmaxf(hv[0][3], hv[1][3]), fmaxf(hv[2][3], hv[3][3]));
        contrib = m0 * w4.x + m1 * w4.y + m2 * w4.z + m3 * w4.w;
    }
    return contrib;
}

// Dense contribution of the final hidden state h_{T-1} at position p.
__device__ __forceinline__ float pool_last(int p, int b, const float* __restrict__ dw)
{
    const int i = p / WP;
    const int j = p % WP;
    if ((i & 1) | (j & 1) || i >= 94 || j >= 94) return 0.f;
    const float* hlast = g_h[(TT - 1) & 1] + (size_t)b * NPOS * FF;
    float m0 = -1e30f, m1 = -1e30f, m2 = -1e30f, m3 = -1e30f;
    #pragma unroll
    for (int di = 0; di < 2; di++)
    #pragma unroll
    for (int dj = 0; dj < 2; dj++) {
        const float4 h4 = *(const float4*)(hlast + ((size_t)((i + di) * WP + (j + dj))) * 4);
        m0 = fmaxf(m0, h4.x); m1 = fmaxf(m1, h4.y);
        m2 = fmaxf(m2, h4.z); m3 = fmaxf(m3, h4.w);
    }
    const int ph = i >> 1, pw = j >> 1;
    const float4 w4 = *(const float4*)(dw + ((((size_t)(TT - 1) * PH + ph) * PW + pw) * 4));
    return m0 * w4.x + m1 * w4.y + m2 * w4.z + m3 * w4.w;
}

// Spin until neighbor flag reaches target (wrap-safe signed compare).
__device__ __forceinline__ void wait_flag(volatile unsigned* f, unsigned target) {
    while ((int)(*f - target) < 0) __nanosleep(20);
}

__global__ void __launch_bounds__(NTHREADS, 4)
persistent_kernel(const float* __restrict__ x,
                  const float4* __restrict__ Kw,    // 48 float4
                  const float4* __restrict__ RKw,   // 64 float4
                  const float4* __restrict__ bias,  // 4 float4
                  const float* __restrict__ dw,
                  const float* __restrict__ db,
                  float* __restrict__ out)
{
    __shared__ float4 sK[48];
    __shared__ float4 sRK[64];
    __shared__ float4 sB[4];
    __shared__ float warpsum[NTHREADS / 32];

    const int tid = threadIdx.x;
    const int b   = blockIdx.y;
    const int blk = blockIdx.x;

    // Monotonic base: own flag, written only by this CTA. All flags are equal
    // at every launch (each advances exactly TT per replay from 0), so bases
    // are uniform across CTAs and comparisons against base+t are consistent.
    const unsigned base = g_flag[b][blk][0];

    if (tid < 48) sK[tid]  = Kw[tid];
    if (tid < 64) sRK[tid] = RKw[tid];
    if (tid < 4)  sB[tid]  = bias[tid];
    __syncthreads();

    const int p = blk * NTHREADS + tid;
    const bool active = (p < NPOS);

    float dense_acc = 0.f;

    for (int t = 0; t < TT; t++) {
        if (t > 0) {
            // RAW: blk+1 must have finished step t-1 (we read its h rows).
            // WAR: blk-1 must have finished step t-1 (it read the buffer we
            //      are about to overwrite, h_{t-2}).
            if (tid == 0) {
                const unsigned tgt = base + (unsigned)t;
                if (blk > 0)         wait_flag(&g_flag[b][blk - 1][0], tgt);
                if (blk + 1 < NBLKX) wait_flag(&g_flag[b][blk + 1][0], tgt);
                __threadfence();     // acquire neighbor h stores
            }
            __syncthreads();
        }

        if (active)
            dense_acc += step_pos(p, b, t, x, sK, sRK, sB, dw);

        __threadfence();             // each thread: release its h/c stores
        __syncthreads();
        if (tid == 0)
            g_flag[b][blk][0] = base + (unsigned)(t + 1);   // publish step done
    }

    // Epilogue RAW: pool_last reads h_{T-1} rows owned by blk+1.
    if (tid == 0) {
        if (blk + 1 < NBLKX) wait_flag(&g_flag[b][blk + 1][0], base + TT);
        __threadfence();
    }
    __syncthreads();

    if (active)
        dense_acc += pool_last(p, b, dw);

    // Deterministic block reduction -> one scratch write per CTA.
    #pragma unroll
    for (int off = 16; off > 0; off >>= 1)
        dense_acc += __shfl_down_sync(0xFFFFFFFFu, dense_acc, off);
    if ((tid & 31) == 0) warpsum[tid >> 5] = dense_acc;
    __syncthreads();
    if (tid == 0) {
        float s = 0.f;
        #pragma unroll
        for (int w = 0; w < NTHREADS / 32; w++) s += warpsum[w];
        g_scratch[b * NBLKX + blk] = s;

        // Per-batch completion: last CTA of batch b emits out[b].
        __threadfence();
        const unsigned old = atomicAdd(&g_done[b], 1u);
        if (old == (unsigned)(NBLKX - 1)) {
            atomicExch(&g_done[b], 0u);   // self-reset for next replay
            __threadfence();
            float acc = 0.f;
            for (int k = 0; k < NBLKX; k++) acc += g_scratch[b * NBLKX + k];
            out[b] = acc + db[0];
        }
    }
}

extern "C" void kernel_launch(void* const* d_in, const int* in_sizes, int n_in,
                              void* d_out, int out_size) {
    const float*  x    = (const float*)d_in[0];
    const float4* Kw   = (const float4*)d_in[1];
    const float4* RKw  = (const float4*)d_in[2];
    const float4* bias = (const float4*)d_in[3];
    const float*  dw   = (const float*)d_in[4];
    const float*  db   = (const float*)d_in[5];
    float* out = (float*)d_out;

    dim3 grid(NBLKX, BB);
    persistent_kernel<<<grid, NTHREADS>>>(x, Kw, RKw, bias, dw, db, out);
}

// round 11
// speedup vs baseline: 3.7133x; 1.0299x over previous
#include <cuda_runtime.h>

// ---------------- problem constants ----------------
#define BB 16          // batch
#define TT 20          // timesteps
#define HH 96
#define WW 96
#define CC 3           // in channels
#define FF 4           // filters
#define HP 95          // valid conv out
#define WP 95
#define PH 47          // pooled
#define PW 47
#define NPOS (HP*WP)   // 9025
#define NTHREADS 256
#define NBLKX 36       // ceil(9025 / 256)
#define NCTAS (NBLKX * BB)   // 576; 148 SMs * 4 CTAs/SM = 592 slots -> all co-resident

// ---------------- persistent device scratch (no allocs allowed) ----------------
__device__ float g_h[2][BB * NPOS * FF];     // ping-pong hidden state
__device__ float g_c[BB * NPOS * FF];        // cell state (updated in place)
__device__ float g_scratch[BB * NBLKX];      // per-block dense partial (written once)
// Per-CTA monotonic step flags, padded to 32B sectors to decouple spin traffic.
__device__ volatile unsigned g_flag[BB][NBLKX][8];
__device__ unsigned g_done[BB];              // per-batch arrival counters (self-reset)

__device__ __forceinline__ float ftanh(float x) {
    float y;
    asm("tanh.approx.f32 %0, %1;" : "=f"(y) : "f"(x));
    return y;
}
__device__ __forceinline__ float fsig(float x) {
    return fmaf(ftanh(0.5f * x), 0.5f, 0.5f);
}

// ---- packed fp32x2 helpers (Blackwell dual-fp32 path; PTX-only) ----
__device__ __forceinline__ unsigned long long dup2(float v) {
    unsigned long long r;
    asm("mov.b64 %0, {%1, %1};" : "=l"(r) : "f"(v));
    return r;
}
__device__ __forceinline__ void fma2(unsigned long long& a,
                                     unsigned long long v, unsigned long long w) {
    asm("fma.rn.f32x2 %0, %1, %2, %0;" : "+l"(a) : "l"(v), "l"(w));
}
__device__ __forceinline__ float2 unpack2(unsigned long long a) {
    float lo, hi;
    asm("mov.b64 {%0, %1}, %2;" : "=f"(lo), "=f"(hi) : "l"(a));
    return make_float2(lo, hi);
}

// One position of one timestep. Gate accumulation uses packed f32x2 FMA:
// zp[k] holds gates {2k, 2k+1}; each smem float4 (16B, LDS.128) is read as
// ulonglong2 = two f32x2 weight pairs. Same accumulation order as the scalar
// version -> bit-identical results. Returns this position's dense contribution.
__device__ __forceinline__ float step_pos(
    int p, int b, int t,
    const float* __restrict__ x,
    const float4* __restrict__ sK, const float4* __restrict__ sRK,
    const float4* __restrict__ sB, const float* __restrict__ dw)
{
    const int i = p / WP;
    const int j = p % WP;

    const float* hprev = g_h[(t + 1) & 1] + (size_t)b * NPOS * FF;
    float*       hnew  = g_h[t & 1]       + (size_t)b * NPOS * FF;
    float*       cc    = g_c              + (size_t)b * NPOS * FF;

    unsigned long long zp[8];   // 16 gate pre-activations as 8 f32x2 pairs
    #pragma unroll
    for (int h = 0; h < 4; h++) {
        const ulonglong2 bb = ((const ulonglong2*)sB)[h];
        zp[2 * h] = bb.x; zp[2 * h + 1] = bb.y;
    }

    // ---- input conv (VALID): rows i,i+1 / cols j,j+1 always in-bounds ----
    const float* xb = x + ((((size_t)b * TT + t) * HH + i) * WW + j) * CC;
    #pragma unroll
    for (int q = 0; q < 4; q++) {
        const int di = q >> 1, dj = q & 1;
        const float* xp = xb + (di * WW + dj) * CC;
        #pragma unroll
        for (int ci = 0; ci < CC; ci++) {
            const unsigned long long vv = dup2(xp[ci]);
            const ulonglong2* kw = (const ulonglong2*)&sK[(q * 3 + ci) * 4];
            #pragma unroll
            for (int h = 0; h < 4; h++) {
                const ulonglong2 w = kw[h];        // gates 4h..4h+3
                fma2(zp[2 * h],     vv, w.x);
                fma2(zp[2 * h + 1], vv, w.y);
            }
        }
    }

    // ---- recurrent conv (SAME, pad_hi=1): h_prev[i+di, j+dj], zeros OOB ----
    float hv[4][4];
    if (t > 0) {
        #pragma unroll
        for (int q = 0; q < 4; q++) {
            const int di = q >> 1, dj = q & 1;
            const int ii = i + di, jj = j + dj;
            float4 h4 = make_float4(0.f, 0.f, 0.f, 0.f);
            if (ii < HP && jj < WP)
                h4 = *(const float4*)(hprev + ((size_t)(ii * WP + jj)) * 4);
            hv[q][0] = h4.x; hv[q][1] = h4.y; hv[q][2] = h4.z; hv[q][3] = h4.w;
            #pragma unroll
            for (int f = 0; f < 4; f++) {
                const unsigned long long vv = dup2(hv[q][f]);
                const ulonglong2* rw = (const ulonglong2*)&sRK[(q * 4 + f) * 4];
                #pragma unroll
                for (int h = 0; h < 4; h++) {
                    const ulonglong2 w = rw[h];
                    fma2(zp[2 * h],     vv, w.x);
                    fma2(zp[2 * h + 1], vv, w.y);
                }
            }
        }
    }

    // ---- gates (order i,f,g,o) + state update ----
    float4 cold = make_float4(0.f, 0.f, 0.f, 0.f);
    if (t > 0) cold = *(const float4*)(cc + (size_t)p * 4);
    const float2 a0 = unpack2(zp[0]), a1 = unpack2(zp[1]);
    const float2 b0 = unpack2(zp[2]), b1 = unpack2(zp[3]);
    const float2 c0 = unpack2(zp[4]), c1 = unpack2(zp[5]);
    const float2 d0 = unpack2(zp[6]), d1 = unpack2(zp[7]);
    const float zi[4] = {a0.x, a0.y, a1.x, a1.y};
    const float zf[4] = {b0.x, b0.y, b1.x, b1.y};
    const float zg[4] = {c0.x, c0.y, c1.x, c1.y};
    const float zo[4] = {d0.x, d0.y, d1.x, d1.y};
    const float cprev[4] = {cold.x, cold.y, cold.z, cold.w};
    float cn[4], hn[4];
    #pragma unroll
    for (int f = 0; f < 4; f++) {
        const float ig = fsig(zi[f]);
        const float fg = fsig(zf[f]);
        const float gg = ftanh(zg[f]);
        const float og = fsig(zo[f]);
        const float c2 = fg * cprev[f] + ig * gg;
        cn[f] = c2;
        hn[f] = og * ftanh(c2);
    }
    *(float4*)(cc   + (size_t)p * 4) = make_float4(cn[0], cn[1], cn[2], cn[3]);
    *(float4*)(hnew + (size_t)p * 4) = make_float4(hn[0], hn[1], hn[2], hn[3]);

    // ---- maxpool(2x2) + dense contribution of h_{t-1} (patch already loaded) ----
    float contrib = 0.f;
    if (t > 0 && ((i & 1) == 0) && ((j & 1) == 0) && i < 94 && j < 94) {
        const int ph = i >> 1, pw = j >> 1;
        const float4 w4 = *(const float4*)(dw + ((((size_t)(t - 1) * PH + ph) * PW + pw) * 4));
        const float m0 = fmaxf(fmaxf(hv[0][0], hv[1][0]), fmaxf(hv[2][0], hv[3][0]));
        const float m1 = fmaxf(fmaxf(hv[0][1], hv[1][1]), fmaxf(hv[2][1], hv[3][1]));
        const float m2 = fmaxf(fmaxf(hv[0][2], hv[1][2]), fmaxf(hv[2][2], hv[3][2]));
        const float m3 = fmaxf(fmaxf(hv[0][3], hv[1][3]), fmaxf(hv[2][3], hv[3][3]));
        contrib = m0 * w4.x + m1 * w4.y + m2 * w4.z + m3 * w4.w;
    }
    return contrib;
}

// Dense contribution of the final hidden state h_{T-1} at position p.
__device__ __forceinline__ float pool_last(int p, int b, const float* __restrict__ dw)
{
    const int i = p / WP;
    const int j = p % WP;
    if ((i & 1) | (j & 1) || i >= 94 || j >= 94) return 0.f;
    const float* hlast = g_h[(TT - 1) & 1] + (size_t)b * NPOS * FF;
    float m0 = -1e30f, m1 = -1e30f, m2 = -1e30f, m3 = -1e30f;
    #pragma unroll
    for (int di = 0; di < 2; di++)
    #pragma unroll
    for (int dj = 0; dj < 2; dj++) {
        const float4 h4 = *(const float4*)(hlast + ((size_t)((i + di) * WP + (j + dj))) * 4);
        m0 = fmaxf(m0, h4.x); m1 = fmaxf(m1, h4.y);
        m2 = fmaxf(m2, h4.z); m3 = fmaxf(m3, h4.w);
    }
    const int ph = i >> 1, pw = j >> 1;
    const float4 w4 = *(const float4*)(dw + ((((size_t)(TT - 1) * PH + ph) * PW + pw) * 4));
    return m0 * w4.x + m1 * w4.y + m2 * w4.z + m3 * w4.w;
}

// Spin until neighbor flag reaches target (wrap-safe signed compare).
__device__ __forceinline__ void wait_flag(volatile unsigned* f, unsigned target) {
    while ((int)(*f - target) < 0) __nanosleep(20);
}

__global__ void __launch_bounds__(NTHREADS, 4)
persistent_kernel(const float* __restrict__ x,
                  const float4* __restrict__ Kw,    // 48 float4
                  const float4* __restrict__ RKw,   // 64 float4
                  const float4* __restrict__ bias,  // 4 float4
                  const float* __restrict__ dw,
                  const float* __restrict__ db,
                  float* __restrict__ out)
{
    __shared__ float4 sK[48];
    __shared__ float4 sRK[64];
    __shared__ float4 sB[4];
    __shared__ float warpsum[NTHREADS / 32];

    const int tid = threadIdx.x;
    const int b   = blockIdx.y;
    const int blk = blockIdx.x;

    // Monotonic base: own flag, written only by this CTA. All flags are equal
    // at every launch (each advances exactly TT per replay from 0), so bases
    // are uniform across CTAs and comparisons against base+t are consistent.
    const unsigned base = g_flag[b][blk][0];

    if (tid < 48) sK[tid]  = Kw[tid];
    if (tid < 64) sRK[tid] = RKw[tid];
    if (tid < 4)  sB[tid]  = bias[tid];
    __syncthreads();

    const int p = blk * NTHREADS + tid;
    const bool active = (p < NPOS);

    float dense_acc = 0.f;

    for (int t = 0; t < TT; t++) {
        if (t > 0) {
            // RAW: blk+1 must have finished step t-1 (we read its h rows).
            // WAR: blk-1 must have finished step t-1 (it read the buffer we
            //      are about to overwrite, h_{t-2}).
            if (tid == 0) {
                const unsigned tgt = base + (unsigned)t;
                if (blk > 0)         wait_flag(&g_flag[b][blk - 1][0], tgt);
                if (blk + 1 < NBLKX) wait_flag(&g_flag[b][blk + 1][0], tgt);
                __threadfence();     // acquire neighbor h stores
            }
            __syncthreads();
        }

        if (active)
            dense_acc += step_pos(p, b, t, x, sK, sRK, sB, dw);

        __threadfence();             // each thread: release its h/c stores
        __syncthreads();
        if (tid == 0)
            g_flag[b][blk][0] = base + (unsigned)(t + 1);   // publish step done
    }

    // Epilogue RAW: pool_last reads h_{T-1} rows owned by blk+1.
    if (tid == 0) {
        if (blk + 1 < NBLKX) wait_flag(&g_flag[b][blk + 1][0], base + TT);
        __threadfence();
    }
    __syncthreads();

    if (active)
        dense_acc += pool_last(p, b, dw);

    // Deterministic block reduction -> one scratch write per CTA.
    #pragma unroll
    for (int off = 16; off > 0; off >>= 1)
        dense_acc += __shfl_down_sync(0xFFFFFFFFu, dense_acc, off);
    if ((tid & 31) == 0) warpsum[tid >> 5] = dense_acc;
    __syncthreads();
    if (tid == 0) {
        float s = 0.f;
        #pragma unroll
        for (int w = 0; w < NTHREADS / 32; w++) s += warpsum[w];
        g_scratch[b * NBLKX + blk] = s;

        // Per-batch completion: last CTA of batch b emits out[b].
        __threadfence();
        const unsigned old = atomicAdd(&g_done[b], 1u);
        if (old == (unsigned)(NBLKX - 1)) {
            atomicExch(&g_done[b], 0u);   // self-reset for next replay
            __threadfence();
            float acc = 0.f;
            for (int k = 0; k < NBLKX; k++) acc += g_scratch[b * NBLKX + k];
            out[b] = acc + db[0];
        }
    }
}

extern "C" void kernel_launch(void* const* d_in, const int* in_sizes, int n_in,
                              void* d_out, int out_size) {
    const float*  x    = (const float*)d_in[0];
    const float4* Kw   = (const float4*)d_in[1];
    const float4* RKw  = (const float4*)d_in[2];
    const float4* bias = (const float4*)d_in[3];
    const float*  dw   = (const float*)d_in[4];
    const float*  db   = (const float*)d_in[5];
    float* out = (float*)d_out;

    dim3 grid(NBLKX, BB);
    persistent_kernel<<<grid, NTHREADS>>>(x, Kw, RKw, bias, dw, db, out);
}

// round 12
// speedup vs baseline: 4.6296x; 1.2468x over previous
#include <cuda_runtime.h>

// ---------------- problem constants ----------------
#define BB 16          // batch
#define TT 20          // timesteps
#define HH 96
#define WW 96
#define CC 3           // in channels
#define FF 4           // filters
#define HP 95          // valid conv out
#define WP 95
#define PH 47          // pooled
#define PW 47
#define NPOS (HP*WP)   // 9025
#define NTHREADS 256
#define NBLKX 36       // ceil(9025 / 256)
#define NCTAS (NBLKX * BB)   // 576; 148 SMs * 4 CTAs/SM = 592 slots -> all co-resident

// ---------------- persistent device scratch (no allocs allowed) ----------------
__device__ float g_h[2][BB * NPOS * FF];     // ping-pong hidden state
__device__ float g_scratch[BB * NBLKX];      // per-block dense partial (written once)
// Per-CTA monotonic step flags, padded to 32B sectors to decouple spin traffic.
__device__ unsigned g_flag[BB][NBLKX][8];
__device__ unsigned g_done[BB];              // per-batch arrival counters (self-reset)

__device__ __forceinline__ float ftanh(float x) {
    float y;
    asm("tanh.approx.f32 %0, %1;" : "=f"(y) : "f"(x));
    return y;
}
__device__ __forceinline__ float fsig(float x) {
    return fmaf(ftanh(0.5f * x), 0.5f, 0.5f);
}

// ---- packed fp32x2 helpers (Blackwell dual-fp32 path; PTX-only) ----
__device__ __forceinline__ unsigned long long dup2(float v) {
    unsigned long long r;
    asm("mov.b64 %0, {%1, %1};" : "=l"(r) : "f"(v));
    return r;
}
__device__ __forceinline__ void fma2(unsigned long long& a,
                                     unsigned long long v, unsigned long long w) {
    asm("fma.rn.f32x2 %0, %1, %2, %0;" : "+l"(a) : "l"(v), "l"(w));
}
__device__ __forceinline__ float2 unpack2(unsigned long long a) {
    float lo, hi;
    asm("mov.b64 {%0, %1}, %2;" : "=f"(lo), "=f"(hi) : "l"(a));
    return make_float2(lo, hi);
}

// ---- gpu-scope release/acquire flag ops (CG grid-sync pattern) ----
__device__ __forceinline__ void st_release(unsigned* f, unsigned v) {
    asm volatile("st.release.gpu.u32 [%0], %1;" :: "l"(f), "r"(v) : "memory");
}
__device__ __forceinline__ unsigned ld_acquire(unsigned* f) {
    unsigned v;
    asm volatile("ld.acquire.gpu.u32 %0, [%1];" : "=r"(v) : "l"(f) : "memory");
    return v;
}
__device__ __forceinline__ void wait_flag(unsigned* f, unsigned target) {
    while ((int)(ld_acquire(f) - target) < 0) __nanosleep(20);
}

// bias + input conv (VALID) for (p, t) -> zp[8] packed gate pre-activations.
// Depends only on x; runs in the neighbor-skew shadow after publishing step t-1.
__device__ __forceinline__ void input_conv(
    unsigned long long* zp, const float* __restrict__ x, int b, int t,
    int i, int j, const float4* __restrict__ sK, const float4* __restrict__ sB)
{
    #pragma unroll
    for (int h = 0; h < 4; h++) {
        const ulonglong2 bb = ((const ulonglong2*)sB)[h];
        zp[2 * h] = bb.x; zp[2 * h + 1] = bb.y;
    }
    const float* xb = x + ((((size_t)b * TT + t) * HH + i) * WW + j) * CC;
    #pragma unroll
    for (int q = 0; q < 4; q++) {
        const int di = q >> 1, dj = q & 1;
        const float* xp = xb + (di * WW + dj) * CC;
        #pragma unroll
        for (int ci = 0; ci < CC; ci++) {
            const unsigned long long vv = dup2(xp[ci]);
            const ulonglong2* kw = (const ulonglong2*)&sK[(q * 3 + ci) * 4];
            #pragma unroll
            for (int h = 0; h < 4; h++) {
                const ulonglong2 w = kw[h];
                fma2(zp[2 * h],     vv, w.x);
                fma2(zp[2 * h + 1], vv, w.y);
            }
        }
    }
}

__global__ void __launch_bounds__(NTHREADS, 4)
persistent_kernel(const float* __restrict__ x,
                  const float4* __restrict__ Kw,    // 48 float4
                  const float4* __restrict__ RKw,   // 64 float4
                  const float4* __restrict__ bias,  // 4 float4
                  const float* __restrict__ dw,
                  const float* __restrict__ db,
                  float* __restrict__ out)
{
    __shared__ float4 sK[48];
    __shared__ float4 sRK[64];
    __shared__ float4 sB[4];
    __shared__ float warpsum[NTHREADS / 32];

    const int tid = threadIdx.x;
    const int b   = blockIdx.y;
    const int blk = blockIdx.x;

    // Monotonic base: own flag (written only by this CTA; +TT per replay).
    const unsigned base = ld_acquire(&g_flag[b][blk][0]);

    if (tid < 48) sK[tid]  = Kw[tid];
    if (tid < 64) sRK[tid] = RKw[tid];
    if (tid < 4)  sB[tid]  = bias[tid];
    __syncthreads();

    const int p = blk * NTHREADS + tid;
    const bool active = (p < NPOS);
    const int i = p / WP;
    const int j = p % WP;

    // Thread-private recurrent state (fixed thread<->position mapping).
    float creg[4] = {0.f, 0.f, 0.f, 0.f};   // c_{t-1}[p]
    float hreg[4] = {0.f, 0.f, 0.f, 0.f};   // h_{t-1}[p]
    float dense_acc = 0.f;

    unsigned long long zp[8];                // bias + input conv, staged for step t
    if (active) input_conv(zp, x, b, 0, i, j, sK, sB);

    for (int t = 0; t < TT; t++) {
        if (t > 0) {
            // RAW: blk+1 finished step t-1 (we read its h rows).
            // WAR: blk-1 finished step t-1 (it read the h_{t-2} buffer we overwrite).
            if (tid == 0) {
                const unsigned tgt = base + (unsigned)t;
                if (blk > 0)         wait_flag(&g_flag[b][blk - 1][0], tgt);
                if (blk + 1 < NBLKX) wait_flag(&g_flag[b][blk + 1][0], tgt);
            }
            __syncthreads();
        }

        if (active) {
            const float* hprev = g_h[(t + 1) & 1] + (size_t)b * NPOS * FF;
            float*       hnew  = g_h[t & 1]       + (size_t)b * NPOS * FF;

            float m0 = 0.f, m1 = 0.f, m2 = 0.f, m3 = 0.f;  // running patch max
            if (t > 0) {
                // q=0: own h_{t-1}[p] is already in registers.
                m0 = hreg[0]; m1 = hreg[1]; m2 = hreg[2]; m3 = hreg[3];
                #pragma unroll
                for (int f = 0; f < 4; f++) {
                    const unsigned long long vv = dup2(hreg[f]);
                    const ulonglong2* rw = (const ulonglong2*)&sRK[f * 4];
                    #pragma unroll
                    for (int h = 0; h < 4; h++) {
                        const ulonglong2 w = rw[h];
                        fma2(zp[2 * h],     vv, w.x);
                        fma2(zp[2 * h + 1], vv, w.y);
                    }
                }
                // q=1..3: neighbor h from global (zeros OOB, SAME pad_hi=1).
                #pragma unroll
                for (int q = 1; q < 4; q++) {
                    const int di = q >> 1, dj = q & 1;
                    const int ii = i + di, jj = j + dj;
                    float4 h4 = make_float4(0.f, 0.f, 0.f, 0.f);
                    if (ii < HP && jj < WP)
                        h4 = *(const float4*)(hprev + ((size_t)(ii * WP + jj)) * 4);
                    m0 = fmaxf(m0, h4.x); m1 = fmaxf(m1, h4.y);
                    m2 = fmaxf(m2, h4.z); m3 = fmaxf(m3, h4.w);
                    const float hvq[4] = {h4.x, h4.y, h4.z, h4.w};
                    #pragma unroll
                    for (int f = 0; f < 4; f++) {
                        const unsigned long long vv = dup2(hvq[f]);
                        const ulonglong2* rw = (const ulonglong2*)&sRK[(q * 4 + f) * 4];
                        #pragma unroll
                        for (int h = 0; h < 4; h++) {
                            const ulonglong2 w = rw[h];
                            fma2(zp[2 * h],     vv, w.x);
                            fma2(zp[2 * h + 1], vv, w.y);
                        }
                    }
                }
            }

            // ---- gates (order i,f,g,o) + state update; c stays in registers ----
            const float2 a0 = unpack2(zp[0]), a1 = unpack2(zp[1]);
            const float2 b0 = unpack2(zp[2]), b1 = unpack2(zp[3]);
            const float2 c0 = unpack2(zp[4]), c1 = unpack2(zp[5]);
            const float2 d0 = unpack2(zp[6]), d1 = unpack2(zp[7]);
            const float zi[4] = {a0.x, a0.y, a1.x, a1.y};
            const float zf[4] = {b0.x, b0.y, b1.x, b1.y};
            const float zg[4] = {c0.x, c0.y, c1.x, c1.y};
            const float zo[4] = {d0.x, d0.y, d1.x, d1.y};
            #pragma unroll
            for (int f = 0; f < 4; f++) {
                const float ig = fsig(zi[f]);
                const float fg = fsig(zf[f]);
                const float gg = ftanh(zg[f]);
                const float og = fsig(zo[f]);
                const float c2 = fg * creg[f] + ig * gg;
                creg[f] = c2;
                hreg[f] = og * ftanh(c2);
            }
            *(float4*)(hnew + (size_t)p * 4) =
                make_float4(hreg[0], hreg[1], hreg[2], hreg[3]);

            // ---- maxpool(2x2) + dense contribution of h_{t-1} ----
            if (t > 0 && ((i & 1) == 0) && ((j & 1) == 0) && i < 94 && j < 94) {
                const int ph = i >> 1, pw = j >> 1;
                const float4 w4 = *(const float4*)(dw + ((((size_t)(t - 1) * PH + ph) * PW + pw) * 4));
                dense_acc += m0 * w4.x + m1 * w4.y + m2 * w4.z + m3 * w4.w;
            }
        }

        __syncthreads();
        if (tid == 0)
            st_release(&g_flag[b][blk][0], base + (unsigned)(t + 1));  // publish

        // Stage step t+1's x-dependent work in the neighbor-skew shadow.
        if (t + 1 < TT && active)
            input_conv(zp, x, b, t + 1, i, j, sK, sB);
    }

    // Epilogue RAW: pool of h_{T-1}; own value in hreg, neighbors via blk+1 flag.
    if (tid == 0) {
        if (blk + 1 < NBLKX) wait_flag(&g_flag[b][blk + 1][0], base + TT);
    }
    __syncthreads();

    if (active && ((i & 1) | (j & 1)) == 0 && i < 94 && j < 94) {
        const float* hlast = g_h[(TT - 1) & 1] + (size_t)b * NPOS * FF;
        float m0 = hreg[0], m1 = hreg[1], m2 = hreg[2], m3 = hreg[3];
        #pragma unroll
        for (int q = 1; q < 4; q++) {
            const int di = q >> 1, dj = q & 1;
            const float4 h4 = *(const float4*)(hlast + ((size_t)((i + di) * WP + (j + dj))) * 4);
            m0 = fmaxf(m0, h4.x); m1 = fmaxf(m1, h4.y);
            m2 = fmaxf(m2, h4.z); m3 = fmaxf(m3, h4.w);
        }
        const int ph = i >> 1, pw = j >> 1;
        const float4 w4 = *(const float4*)(dw + ((((size_t)(TT - 1) * PH + ph) * PW + pw) * 4));
        dense_acc += m0 * w4.x + m1 * w4.y + m2 * w4.z + m3 * w4.w;
    }

    // Deterministic block reduction -> one scratch write per CTA.
    #pragma unroll
    for (int off = 16; off > 0; off >>= 1)
        dense_acc += __shfl_down_sync(0xFFFFFFFFu, dense_acc, off);
    if ((tid & 31) == 0) warpsum[tid >> 5] = dense_acc;
    __syncthreads();
    if (tid == 0) {
        float s = 0.f;
        #pragma unroll
        for (int w = 0; w < NTHREADS / 32; w++) s += warpsum[w];
        g_scratch[b * NBLKX + blk] = s;

        // Per-batch completion: last CTA of batch b emits out[b].
        __threadfence();
        const unsigned old = atomicAdd(&g_done[b], 1u);
        if (old == (unsigned)(NBLKX - 1)) {
            atomicExch(&g_done[b], 0u);   // self-reset for next replay
            __threadfence();
            float acc = 0.f;
            for (int k = 0; k < NBLKX; k++) acc += g_scratch[b * NBLKX + k];
            out[b] = acc + db[0];
        }
    }
}

extern "C" void kernel_launch(void* const* d_in, const int* in_sizes, int n_in,
                              void* d_out, int out_size) {
    const float*  x    = (const float*)d_in[0];
    const float4* Kw   = (const float4*)d_in[1];
    const float4* RKw  = (const float4*)d_in[2];
    const float4* bias = (const float4*)d_in[3];
    const float*  dw   = (const float*)d_in[4];
    const float*  db   = (const float*)d_in[5];
    float* out = (float*)d_out;

    dim3 grid(NBLKX, BB);
    persistent_kernel<<<grid, NTHREADS>>>(x, Kw, RKw, bias, dw, db, out);
}

// round 13
// speedup vs baseline: 5.5700x; 1.2031x over previous
#include <cuda_runtime.h>

// ---------------- problem constants ----------------
#define BB 16          // batch
#define TT 20          // timesteps
#define HH 96
#define WW 96
#define CC 3           // in channels
#define FF 4           // filters
#define HP 95          // valid conv out
#define WP 95
#define PH 47          // pooled
#define PW 47
#define NPOS (HP*WP)   // 9025
#define NTHREADS 128   // threads per CTA; each thread owns 2 positions
#define POSPC 256      // positions per CTA (same coverage as before)
#define NBLKX 36       // ceil(9025 / 256)
#define NCTAS (NBLKX * BB)   // 576; 4 CTAs/SM * 148 = 592 slots -> all co-resident

// ---------------- persistent device scratch (no allocs allowed) ----------------
__device__ float g_h[2][BB * NPOS * FF];     // ping-pong hidden state
__device__ float g_scratch[BB * NBLKX];      // per-block dense partial (written once)
// Per-CTA monotonic step flags, padded to 32B sectors to decouple spin traffic.
__device__ unsigned g_flag[BB][NBLKX][8];
__device__ unsigned g_done[BB];              // per-batch arrival counters (self-reset)

__device__ __forceinline__ float ftanh(float x) {
    float y;
    asm("tanh.approx.f32 %0, %1;" : "=f"(y) : "f"(x));
    return y;
}
__device__ __forceinline__ float fsig(float x) {
    return fmaf(ftanh(0.5f * x), 0.5f, 0.5f);
}

// ---- packed fp32x2 helpers (Blackwell dual-fp32 path; PTX-only) ----
__device__ __forceinline__ unsigned long long dup2(float v) {
    unsigned long long r;
    asm("mov.b64 %0, {%1, %1};" : "=l"(r) : "f"(v));
    return r;
}
__device__ __forceinline__ void fma2(unsigned long long& a,
                                     unsigned long long v, unsigned long long w) {
    asm("fma.rn.f32x2 %0, %1, %2, %0;" : "+l"(a) : "l"(v), "l"(w));
}
__device__ __forceinline__ float2 unpack2(unsigned long long a) {
    float lo, hi;
    asm("mov.b64 {%0, %1}, %2;" : "=f"(lo), "=f"(hi) : "l"(a));
    return make_float2(lo, hi);
}

// ---- gpu-scope release/acquire flag ops (CG grid-sync pattern) ----
__device__ __forceinline__ void st_release(unsigned* f, unsigned v) {
    asm volatile("st.release.gpu.u32 [%0], %1;" :: "l"(f), "r"(v) : "memory");
}
__device__ __forceinline__ unsigned ld_acquire(unsigned* f) {
    unsigned v;
    asm volatile("ld.acquire.gpu.u32 %0, [%1];" : "=r"(v) : "l"(f) : "memory");
    return v;
}
__device__ __forceinline__ void wait_flag(unsigned* f, unsigned target) {
    while ((int)(ld_acquire(f) - target) < 0) __nanosleep(20);
}

// bias + input conv (VALID) for BOTH positions of this thread at timestep t.
// Weight vectors are loaded ONCE and applied to both positions.
// Runs in the neighbor-skew shadow after publishing the previous step.
__device__ __forceinline__ void input_conv2(
    unsigned long long zp0[8], unsigned long long zp1[8],
    const float* __restrict__ x, int b, int t,
    int i0, int j0, bool a0, int i1, int j1, bool a1,
    const float4* __restrict__ sK, const float4* __restrict__ sB)
{
    #pragma unroll
    for (int h = 0; h < 4; h++) {
        const ulonglong2 bb = ((const ulonglong2*)sB)[h];
        zp0[2 * h] = bb.x; zp0[2 * h + 1] = bb.y;
        zp1[2 * h] = bb.x; zp1[2 * h + 1] = bb.y;
    }
    float xv0[12], xv1[12];
    #pragma unroll
    for (int e = 0; e < 12; e++) { xv0[e] = 0.f; xv1[e] = 0.f; }
    if (a0) {
        const float* xb = x + ((((size_t)b * TT + t) * HH + i0) * WW + j0) * CC;
        #pragma unroll
        for (int q = 0; q < 4; q++)
            #pragma unroll
            for (int ci = 0; ci < CC; ci++)
                xv0[q * 3 + ci] = xb[((q >> 1) * WW + (q & 1)) * CC + ci];
    }
    if (a1) {
        const float* xb = x + ((((size_t)b * TT + t) * HH + i1) * WW + j1) * CC;
        #pragma unroll
        for (int q = 0; q < 4; q++)
            #pragma unroll
            for (int ci = 0; ci < CC; ci++)
                xv1[q * 3 + ci] = xb[((q >> 1) * WW + (q & 1)) * CC + ci];
    }
    #pragma unroll
    for (int e = 0; e < 12; e++) {
        const unsigned long long vv0 = dup2(xv0[e]);
        const unsigned long long vv1 = dup2(xv1[e]);
        const ulonglong2* kw = (const ulonglong2*)&sK[e * 4];
        #pragma unroll
        for (int h = 0; h < 4; h++) {
            const ulonglong2 w = kw[h];            // shared weight load
            fma2(zp0[2 * h],     vv0, w.x);
            fma2(zp0[2 * h + 1], vv0, w.y);
            fma2(zp1[2 * h],     vv1, w.x);
            fma2(zp1[2 * h + 1], vv1, w.y);
        }
    }
}

__global__ void __launch_bounds__(NTHREADS, 4)
persistent_kernel(const float* __restrict__ x,
                  const float4* __restrict__ Kw,    // 48 float4
                  const float4* __restrict__ RKw,   // 64 float4
                  const float4* __restrict__ bias,  // 4 float4
                  const float* __restrict__ dw,
                  const float* __restrict__ db,
                  float* __restrict__ out)
{
    __shared__ float4 sK[48];
    __shared__ float4 sRK[64];
    __shared__ float4 sB[4];
    __shared__ float warpsum[NTHREADS / 32];

    const int tid = threadIdx.x;
    const int b   = blockIdx.y;
    const int blk = blockIdx.x;

    // Monotonic base: own flag (written only by this CTA; +TT per replay).
    const unsigned base = ld_acquire(&g_flag[b][blk][0]);

    if (tid < 48) sK[tid]  = Kw[tid];
    if (tid < 64) sRK[tid] = RKw[tid];
    if (tid < 4)  sB[tid]  = bias[tid];
    __syncthreads();

    const int p0 = blk * POSPC + tid;
    const int p1 = p0 + NTHREADS;
    const bool a0 = (p0 < NPOS);
    const bool a1 = (p1 < NPOS);
    const int i0 = p0 / WP, j0 = p0 % WP;
    const int i1 = p1 / WP, j1 = p1 % WP;

    // Thread-private recurrent state for both positions.
    float creg[2][4] = {{0.f,0.f,0.f,0.f},{0.f,0.f,0.f,0.f}};
    float hreg[2][4] = {{0.f,0.f,0.f,0.f},{0.f,0.f,0.f,0.f}};
    float dense_acc = 0.f;

    unsigned long long zp0[8], zp1[8];       // staged gate pre-activations
    input_conv2(zp0, zp1, x, b, 0, i0, j0, a0, i1, j1, a1, sK, sB);

    for (int t = 0; t < TT; t++) {
        if (t > 0) {
            // RAW: blk+1 finished step t-1 (we read its h rows).
            // WAR: blk-1 finished step t-1 (it read the h_{t-2} buffer we overwrite).
            if (tid == 0) {
                const unsigned tgt = base + (unsigned)t;
                if (blk > 0)         wait_flag(&g_flag[b][blk - 1][0], tgt);
                if (blk + 1 < NBLKX) wait_flag(&g_flag[b][blk + 1][0], tgt);
            }
            __syncthreads();
        }

        const float* hprev = g_h[(t + 1) & 1] + (size_t)b * NPOS * FF;
        float*       hnew  = g_h[t & 1]       + (size_t)b * NPOS * FF;

        float m[2][4];
        #pragma unroll
        for (int s = 0; s < 2; s++)
            #pragma unroll
            for (int f = 0; f < 4; f++) m[s][f] = hreg[s][f];

        if (t > 0) {
            // q=0: own h_{t-1} (registers), weights shared across positions.
            #pragma unroll
            for (int f = 0; f < 4; f++) {
                const unsigned long long vv0 = dup2(hreg[0][f]);
                const unsigned long long vv1 = dup2(hreg[1][f]);
                const ulonglong2* rw = (const ulonglong2*)&sRK[f * 4];
                #pragma unroll
                for (int h = 0; h < 4; h++) {
                    const ulonglong2 w = rw[h];
                    fma2(zp0[2 * h],     vv0, w.x);
                    fma2(zp0[2 * h + 1], vv0, w.y);
                    fma2(zp1[2 * h],     vv1, w.x);
                    fma2(zp1[2 * h + 1], vv1, w.y);
                }
            }
            // q=1..3: neighbor h from global (zeros OOB, SAME pad_hi=1).
            #pragma unroll
            for (int q = 1; q < 4; q++) {
                const int di = q >> 1, dj = q & 1;
                float4 h40 = make_float4(0.f, 0.f, 0.f, 0.f);
                float4 h41 = make_float4(0.f, 0.f, 0.f, 0.f);
                {
                    const int ii = i0 + di, jj = j0 + dj;
                    if (a0 && ii < HP && jj < WP)
                        h40 = *(const float4*)(hprev + ((size_t)(ii * WP + jj)) * 4);
                    const int ii1 = i1 + di, jj1 = j1 + dj;
                    if (a1 && ii1 < HP && jj1 < WP)
                        h41 = *(const float4*)(hprev + ((size_t)(ii1 * WP + jj1)) * 4);
                }
                m[0][0] = fmaxf(m[0][0], h40.x); m[0][1] = fmaxf(m[0][1], h40.y);
                m[0][2] = fmaxf(m[0][2], h40.z); m[0][3] = fmaxf(m[0][3], h40.w);
                m[1][0] = fmaxf(m[1][0], h41.x); m[1][1] = fmaxf(m[1][1], h41.y);
                m[1][2] = fmaxf(m[1][2], h41.z); m[1][3] = fmaxf(m[1][3], h41.w);
                const float hv0[4] = {h40.x, h40.y, h40.z, h40.w};
                const float hv1[4] = {h41.x, h41.y, h41.z, h41.w};
                #pragma unroll
                for (int f = 0; f < 4; f++) {
                    const unsigned long long vv0 = dup2(hv0[f]);
                    const unsigned long long vv1 = dup2(hv1[f]);
                    const ulonglong2* rw = (const ulonglong2*)&sRK[(q * 4 + f) * 4];
                    #pragma unroll
                    for (int h = 0; h < 4; h++) {
                        const ulonglong2 w = rw[h];
                        fma2(zp0[2 * h],     vv0, w.x);
                        fma2(zp0[2 * h + 1], vv0, w.y);
                        fma2(zp1[2 * h],     vv1, w.x);
                        fma2(zp1[2 * h + 1], vv1, w.y);
                    }
                }
            }
        }

        // ---- gates (order i,f,g,o) + state update + h store, per position ----
        #pragma unroll
        for (int s = 0; s < 2; s++) {
            unsigned long long* zp = (s == 0) ? zp0 : zp1;
            const float2 a0v = unpack2(zp[0]), a1v = unpack2(zp[1]);
            const float2 b0v = unpack2(zp[2]), b1v = unpack2(zp[3]);
            const float2 c0v = unpack2(zp[4]), c1v = unpack2(zp[5]);
            const float2 d0v = unpack2(zp[6]), d1v = unpack2(zp[7]);
            const float zi[4] = {a0v.x, a0v.y, a1v.x, a1v.y};
            const float zf[4] = {b0v.x, b0v.y, b1v.x, b1v.y};
            const float zg[4] = {c0v.x, c0v.y, c1v.x, c1v.y};
            const float zo[4] = {d0v.x, d0v.y, d1v.x, d1v.y};
            #pragma unroll
            for (int f = 0; f < 4; f++) {
                const float ig = fsig(zi[f]);
                const float fg = fsig(zf[f]);
                const float gg = ftanh(zg[f]);
                const float og = fsig(zo[f]);
                const float c2 = fg * creg[s][f] + ig * gg;
                creg[s][f] = c2;
                hreg[s][f] = og * ftanh(c2);
            }
            const int  ps = (s == 0) ? p0 : p1;
            const bool as = (s == 0) ? a0 : a1;
            if (as)
                *(float4*)(hnew + (size_t)ps * 4) =
                    make_float4(hreg[s][0], hreg[s][1], hreg[s][2], hreg[s][3]);
        }

        // ---- maxpool(2x2) + dense contribution of h_{t-1}, per position ----
        if (t > 0) {
            #pragma unroll
            for (int s = 0; s < 2; s++) {
                const int  is = (s == 0) ? i0 : i1;
                const int  js = (s == 0) ? j0 : j1;
                const bool as = (s == 0) ? a0 : a1;
                if (as && ((is & 1) | (js & 1)) == 0 && is < 94 && js < 94) {
                    const int ph = is >> 1, pw = js >> 1;
                    const float4 w4 = *(const float4*)(dw +
                        ((((size_t)(t - 1) * PH + ph) * PW + pw) * 4));
                    dense_acc += m[s][0] * w4.x + m[s][1] * w4.y
                               + m[s][2] * w4.z + m[s][3] * w4.w;
                }
            }
        }

        __syncthreads();
        if (tid == 0)
            st_release(&g_flag[b][blk][0], base + (unsigned)(t + 1));  // publish

        // Stage step t+1's x-dependent work in the neighbor-skew shadow.
        if (t + 1 < TT)
            input_conv2(zp0, zp1, x, b, t + 1, i0, j0, a0, i1, j1, a1, sK, sB);
    }

    // Epilogue RAW: pool of h_{T-1}; own values in hreg, neighbors via blk+1 flag.
    if (tid == 0) {
        if (blk + 1 < NBLKX) wait_flag(&g_flag[b][blk + 1][0], base + TT);
    }
    __syncthreads();

    {
        const float* hlast = g_h[(TT - 1) & 1] + (size_t)b * NPOS * FF;
        #pragma unroll
        for (int s = 0; s < 2; s++) {
            const int  is = (s == 0) ? i0 : i1;
            const int  js = (s == 0) ? j0 : j1;
            const bool as = (s == 0) ? a0 : a1;
            if (as && ((is & 1) | (js & 1)) == 0 && is < 94 && js < 94) {
                float m0 = hreg[s][0], m1 = hreg[s][1], m2 = hreg[s][2], m3 = hreg[s][3];
                #pragma unroll
                for (int q = 1; q < 4; q++) {
                    const int di = q >> 1, dj = q & 1;
                    const float4 h4 = *(const float4*)(hlast +
                        ((size_t)((is + di) * WP + (js + dj))) * 4);
                    m0 = fmaxf(m0, h4.x); m1 = fmaxf(m1, h4.y);
                    m2 = fmaxf(m2, h4.z); m3 = fmaxf(m3, h4.w);
                }
                const int ph = is >> 1, pw = js >> 1;
                const float4 w4 = *(const float4*)(dw +
                    ((((size_t)(TT - 1) * PH + ph) * PW + pw) * 4));
                dense_acc += m0 * w4.x + m1 * w4.y + m2 * w4.z + m3 * w4.w;
            }
        }
    }

    // Deterministic block reduction -> one scratch write per CTA.
    #pragma unroll
    for (int off = 16; off > 0; off >>= 1)
        dense_acc += __shfl_down_sync(0xFFFFFFFFu, dense_acc, off);
    if ((tid & 31) == 0) warpsum[tid >> 5] = dense_acc;
    __syncthreads();
    if (tid == 0) {
        float s = 0.f;
        #pragma unroll
        for (int w = 0; w < NTHREADS / 32; w++) s += warpsum[w];
        g_scratch[b * NBLKX + blk] = s;

        // Per-batch completion: last CTA of batch b emits out[b].
        __threadfence();
        const unsigned old = atomicAdd(&g_done[b], 1u);
        if (old == (unsigned)(NBLKX - 1)) {
            atomicExch(&g_done[b], 0u);   // self-reset for next replay
            __threadfence();
            float acc = 0.f;
            for (int k = 0; k < NBLKX; k++) acc += g_scratch[b * NBLKX + k];
            out[b] = acc + db[0];
        }
    }
}

extern "C" void kernel_launch(void* const* d_in, const int* in_sizes, int n_in,
                              void* d_out, int out_size) {
    const float*  x    = (const float*)d_in[0];
    const float4* Kw   = (const float4*)d_in[1];
    const float4* RKw  = (const float4*)d_in[2];
    const float4* bias = (const float4*)d_in[3];
    const float*  dw   = (const float*)d_in[4];
    const float*  db   = (const float*)d_in[5];
    float* out = (float*)d_out;

    dim3 grid(NBLKX, BB);
    persistent_kernel<<<grid, NTHREADS>>>(x, Kw, RKw, bias, dw, db, out);
}